// round 2
// baseline (speedup 1.0000x reference)
#include <cuda_runtime.h>
#include <cuda_bf16.h>

#define NMAX 100000
#define DD 64

// Scratch (device globals; allocation inside kernel_launch is forbidden)
__device__ float g_deg[NMAX];
__device__ float g_dinv[NMAX];
__device__ float g_h[NMAX * DD];    // X @ W (transformed features)
__device__ float g_agg[NMAX * DD];  // layer-1 aggregated output (pre-ReLU)

// ---------------------------------------------------------------------------
// deg[i] = 1 (self loop)
__global__ void k_deg_init(float* deg, int n) {
    int i = blockIdx.x * blockDim.x + threadIdx.x;
    if (i < n) deg[i] = 1.0f;
}

// deg[dst[e]] += 1
__global__ void k_deg_accum(const int* __restrict__ dst, float* deg, int ne) {
    int i = blockIdx.x * blockDim.x + threadIdx.x;
    if (i < ne) {
        float* p = deg + dst[i];
        asm volatile("red.global.add.f32 [%0], %1;" :: "l"(p), "f"(1.0f) : "memory");
    }
}

// dinv[i] = rsqrt(deg[i])   (deg >= 1 always)
__global__ void k_dinv(const float* __restrict__ deg, float* dinv, int n) {
    int i = blockIdx.x * blockDim.x + threadIdx.x;
    if (i < n) dinv[i] = rsqrtf(deg[i]);
}

// ---------------------------------------------------------------------------
// h = f(in) @ W, f = identity or ReLU.  block = (64,4): 4 rows per block.
__global__ void k_gemm(const float* __restrict__ in, const float* __restrict__ W,
                       float* __restrict__ out, int n, int do_relu) {
    __shared__ float Ws[DD * DD];
    __shared__ float xs[4][DD];
    int tx = threadIdx.x, ty = threadIdx.y;
    int tid = ty * DD + tx;
    for (int i = tid; i < DD * DD; i += 256) Ws[i] = W[i];

    int row = blockIdx.x * 4 + ty;
    float v = 0.0f;
    if (row < n) {
        v = in[row * DD + tx];
        if (do_relu) v = fmaxf(v, 0.0f);
    }
    xs[ty][tx] = v;
    __syncthreads();

    if (row >= n) return;
    float acc = 0.0f;
#pragma unroll
    for (int k = 0; k < DD; k++)
        acc = fmaf(xs[ty][k], Ws[k * DD + tx], acc);
    out[row * DD + tx] = acc;
}

// ---------------------------------------------------------------------------
// out[i][j] = h[i][j] * dinv[i]^2 + b[j]   (self-loop message + bias)
__global__ void k_self_bias(const float* __restrict__ h, const float* __restrict__ dinv,
                            const float* __restrict__ b, float* __restrict__ out, int n) {
    int idx = blockIdx.x * blockDim.x + threadIdx.x;
    if (idx >= n * DD) return;
    int row = idx >> 6;
    int col = idx & 63;
    float di = dinv[row];
    out[idx] = h[idx] * di * di + b[col];
}

// ---------------------------------------------------------------------------
// Edge scatter: 16 threads per edge, each handles one float4 of the 64-float row.
// out[dst] += h[src] * dinv[src]*dinv[dst]   via red.global.add.v4.f32
__global__ void k_scatter(const int* __restrict__ src, const int* __restrict__ dst,
                          const float* __restrict__ h, const float* __restrict__ dinv,
                          float* __restrict__ out, int ne) {
    int t = blockIdx.x * blockDim.x + threadIdx.x;
    int e = t >> 4;
    int lane = t & 15;
    if (e >= ne) return;
    int s = __ldg(src + e);
    int d = __ldg(dst + e);
    float norm = __ldg(dinv + s) * __ldg(dinv + d);
    float4 v = __ldg(reinterpret_cast<const float4*>(h + (size_t)s * DD) + lane);
    float4 m;
    m.x = v.x * norm; m.y = v.y * norm; m.z = v.z * norm; m.w = v.w * norm;
    float* op = out + (size_t)d * DD + lane * 4;
    asm volatile("red.global.add.v4.f32 [%0], {%1,%2,%3,%4};"
                 :: "l"(op), "f"(m.x), "f"(m.y), "f"(m.z), "f"(m.w) : "memory");
}

// ---------------------------------------------------------------------------
static void* sym_addr(const void* sym) {
    void* p = nullptr;
    cudaGetSymbolAddress(&p, sym);
    return p;
}

extern "C" void kernel_launch(void* const* d_in, const int* in_sizes, int n_in,
                              void* d_out, int out_size) {
    const float* x  = (const float*)d_in[0];
    const float* W1 = (const float*)d_in[1];
    const float* b1 = (const float*)d_in[2];
    const float* W2 = (const float*)d_in[3];
    const float* b2 = (const float*)d_in[4];
    const int*   e0 = (const int*)d_in[5];   // [2, E] row-major: src then dst
    const int*   e1 = (const int*)d_in[6];

    const int N = in_sizes[0] / DD;
    const int E = in_sizes[5] / 2;

    float* deg  = (float*)sym_addr(g_deg);
    float* dinv = (float*)sym_addr(g_dinv);
    float* h    = (float*)sym_addr(g_h);
    float* agg  = (float*)sym_addr(g_agg);
    float* out  = (float*)d_out;

    const int T = 256;
    dim3 gemm_blk(64, 4);
    int gemm_grid = (N + 3) / 4;
    int nd_grid   = (N * DD + T - 1) / T;
    int n_grid    = (N + T - 1) / T;
    int e_grid    = (E + T - 1) / T;
    int sc_grid   = ((E * 16) + T - 1) / T;

    // ---------------- Layer 1 ----------------
    k_deg_init<<<n_grid, T>>>(deg, N);
    k_deg_accum<<<e_grid, T>>>(e0 + E, deg, E);
    k_dinv<<<n_grid, T>>>(deg, dinv, N);
    k_gemm<<<gemm_grid, gemm_blk>>>(x, W1, h, N, 0);
    k_self_bias<<<nd_grid, T>>>(h, dinv, b1, agg, N);
    k_scatter<<<sc_grid, T>>>(e0, e0 + E, h, dinv, agg, E);

    // ---------------- Layer 2 ----------------
    k_deg_init<<<n_grid, T>>>(deg, N);
    k_deg_accum<<<e_grid, T>>>(e1 + E, deg, E);
    k_dinv<<<n_grid, T>>>(deg, dinv, N);
    k_gemm<<<gemm_grid, gemm_blk>>>(agg, W2, h, N, 1);   // ReLU fused into load
    k_self_bias<<<nd_grid, T>>>(h, dinv, b2, out, N);
    k_scatter<<<sc_grid, T>>>(e1, e1 + E, h, dinv, out, E);
}

// round 5
// speedup vs baseline: 1.3128x; 1.3128x over previous
#include <cuda_runtime.h>
#include <cuda_bf16.h>

#define NMAX 100000
#define DD 64

// Scratch (device globals; allocation inside kernel_launch is forbidden)
__device__ float g_deg[NMAX];
__device__ float g_dinv[NMAX];
__device__ float g_hs[NMAX * DD];   // (X @ W) * dinv[row]  (pre-scaled for scatter)
__device__ float g_agg[NMAX * DD];  // layer-1 aggregated output (pre-ReLU)

// ---------------------------------------------------------------------------
__global__ void k_deg_init(float* deg, int n) {
    int i = blockIdx.x * blockDim.x + threadIdx.x;
    if (i < n) deg[i] = 1.0f;
}

__global__ void k_deg_accum(const int* __restrict__ dst, float* deg, int ne) {
    int i = blockIdx.x * blockDim.x + threadIdx.x;
    if (i < ne) {
        float* p = deg + dst[i];
        asm volatile("red.global.add.f32 [%0], %1;" :: "l"(p), "f"(1.0f) : "memory");
    }
}

__global__ void k_dinv(const float* __restrict__ deg, float* dinv, int n) {
    int i = blockIdx.x * blockDim.x + threadIdx.x;
    if (i < n) dinv[i] = rsqrtf(deg[i]);
}

// ---------------------------------------------------------------------------
// Register-tiled GEMM + fused epilogue.
//   h   = f(in) @ W            (f = identity or ReLU)
//   hs  = h * dinv[row]                       -> for edge gather
//   agg = hs * dinv[row] + b                  -> self-loop message + bias (init of output)
// Block: 256 threads, 256 rows x 64 cols tile.
// Thread (cx=tid&15, ry=tid>>4) computes 16 rows (ry+16i) x 4 cols (cx*4..+3).
#define XPAD 68
__global__ __launch_bounds__(256, 2)
void k_gemm_fused(const float* __restrict__ in, const float* __restrict__ W,
                  const float* __restrict__ b, const float* __restrict__ dinv,
                  float* __restrict__ hs, float* __restrict__ agg,
                  int n, int do_relu) {
    extern __shared__ float smem_f[];
    float* Ws = smem_f;                 // 64*64
    float* xs = smem_f + DD * DD;       // 256*XPAD

    int tid = threadIdx.x;
    int cx = tid & 15;
    int ry = tid >> 4;
    int row0 = blockIdx.x * 256;

    // Load W (row-major, 16KB)
    for (int i = tid; i < DD * DD; i += 256) Ws[i] = W[i];

    // Load 256-row x tile (vectorized, optional ReLU), padded rows
    for (int i = tid; i < 256 * 16; i += 256) {
        int r = i >> 4, c4 = i & 15;
        int grow = row0 + r;
        float4 v = make_float4(0.f, 0.f, 0.f, 0.f);
        if (grow < n) v = __ldg(reinterpret_cast<const float4*>(in + (size_t)grow * DD) + c4);
        if (do_relu) {
            v.x = fmaxf(v.x, 0.f); v.y = fmaxf(v.y, 0.f);
            v.z = fmaxf(v.z, 0.f); v.w = fmaxf(v.w, 0.f);
        }
        *reinterpret_cast<float4*>(&xs[r * XPAD + c4 * 4]) = v;
    }
    __syncthreads();

    float4 acc[16];
#pragma unroll
    for (int i = 0; i < 16; i++) acc[i] = make_float4(0.f, 0.f, 0.f, 0.f);

#pragma unroll 4
    for (int k = 0; k < DD; k++) {
        float4 wv = *reinterpret_cast<const float4*>(&Ws[k * DD + cx * 4]);
#pragma unroll
        for (int i = 0; i < 16; i++) {
            float xv = xs[(ry + 16 * i) * XPAD + k];
            acc[i].x = fmaf(wv.x, xv, acc[i].x);
            acc[i].y = fmaf(wv.y, xv, acc[i].y);
            acc[i].z = fmaf(wv.z, xv, acc[i].z);
            acc[i].w = fmaf(wv.w, xv, acc[i].w);
        }
    }

    float4 bv = __ldg(reinterpret_cast<const float4*>(b) + cx);
#pragma unroll
    for (int i = 0; i < 16; i++) {
        int grow = row0 + ry + 16 * i;
        if (grow >= n) continue;
        float di = __ldg(dinv + grow);
        float4 h4 = acc[i];
        float4 hs4 = make_float4(h4.x * di, h4.y * di, h4.z * di, h4.w * di);
        float4 ag4 = make_float4(fmaf(hs4.x, di, bv.x), fmaf(hs4.y, di, bv.y),
                                 fmaf(hs4.z, di, bv.z), fmaf(hs4.w, di, bv.w));
        *reinterpret_cast<float4*>(hs  + (size_t)grow * DD + cx * 4) = hs4;
        *reinterpret_cast<float4*>(agg + (size_t)grow * DD + cx * 4) = ag4;
    }
}

// ---------------------------------------------------------------------------
// Edge scatter: 16 threads per edge, one float4 each.
// out[dst] += hs[src] * dinv[dst]      (hs is already h*dinv[src])
__global__ void k_scatter(const int* __restrict__ src, const int* __restrict__ dst,
                          const float* __restrict__ hs, const float* __restrict__ dinv,
                          float* __restrict__ out, int ne) {
    int t = blockIdx.x * blockDim.x + threadIdx.x;
    int e = t >> 4;
    int lane = t & 15;
    if (e >= ne) return;
    int s = __ldg(src + e);
    int d = __ldg(dst + e);
    float norm = __ldg(dinv + d);
    float4 v = __ldg(reinterpret_cast<const float4*>(hs + (size_t)s * DD) + lane);
    float4 m;
    m.x = v.x * norm; m.y = v.y * norm; m.z = v.z * norm; m.w = v.w * norm;
    float* op = out + (size_t)d * DD + lane * 4;
    asm volatile("red.global.add.v4.f32 [%0], {%1,%2,%3,%4};"
                 :: "l"(op), "f"(m.x), "f"(m.y), "f"(m.z), "f"(m.w) : "memory");
}

// ---------------------------------------------------------------------------
static void* sym_addr(const void* sym) {
    void* p = nullptr;
    cudaGetSymbolAddress(&p, sym);
    return p;
}

extern "C" void kernel_launch(void* const* d_in, const int* in_sizes, int n_in,
                              void* d_out, int out_size) {
    const float* x  = (const float*)d_in[0];
    const float* W1 = (const float*)d_in[1];
    const float* b1 = (const float*)d_in[2];
    const float* W2 = (const float*)d_in[3];
    const float* b2 = (const float*)d_in[4];
    const int*   e0 = (const int*)d_in[5];   // [2, E]: src row then dst row
    const int*   e1 = (const int*)d_in[6];

    const int N = in_sizes[0] / DD;
    const int E = in_sizes[5] / 2;

    float* deg  = (float*)sym_addr(g_deg);
    float* dinv = (float*)sym_addr(g_dinv);
    float* hs   = (float*)sym_addr(g_hs);
    float* agg  = (float*)sym_addr(g_agg);
    float* out  = (float*)d_out;

    const int T = 256;
    int n_grid  = (N + T - 1) / T;
    int e_grid  = (E + T - 1) / T;
    int sc_grid = ((E * 16) + T - 1) / T;
    int gm_grid = (N + 255) / 256;
    size_t gm_smem = (DD * DD + 256 * XPAD) * sizeof(float);

    static int attr_set = 0;
    if (!attr_set) {
        cudaFuncSetAttribute(k_gemm_fused, cudaFuncAttributeMaxDynamicSharedMemorySize,
                             (int)gm_smem);
        attr_set = 1;
    }

    // ---------------- Layer 1 ----------------
    k_deg_init<<<n_grid, T>>>(deg, N);
    k_deg_accum<<<e_grid, T>>>(e0 + E, deg, E);
    k_dinv<<<n_grid, T>>>(deg, dinv, N);
    k_gemm_fused<<<gm_grid, 256, gm_smem>>>(x, W1, b1, dinv, hs, agg, N, 0);
    k_scatter<<<sc_grid, T>>>(e0, e0 + E, hs, dinv, agg, E);

    // ---------------- Layer 2 ----------------
    k_deg_init<<<n_grid, T>>>(deg, N);
    k_deg_accum<<<e_grid, T>>>(e1 + E, deg, E);
    k_dinv<<<n_grid, T>>>(deg, dinv, N);
    k_gemm_fused<<<gm_grid, 256, gm_smem>>>(agg, W2, b2, dinv, hs, out, N, 1);  // ReLU fused
    k_scatter<<<sc_grid, T>>>(e1, e1 + E, hs, dinv, out, E);
}

// round 9
// speedup vs baseline: 1.9678x; 1.4990x over previous
#include <cuda_runtime.h>
#include <cuda_fp16.h>

#define NMAX 100000
#define EMAX 3200000
#define DD 64
#define SCAN_B 1024

// Scratch (device globals; allocation is forbidden)
__device__ float  g_dinv[NMAX];
__device__ int    g_cnt[NMAX];
__device__ int    g_off[NMAX];
__device__ int    g_cur[NMAX];
__device__ int    g_bsum[(NMAX + SCAN_B - 1) / SCAN_B + 1];
__device__ int    g_csr[EMAX];
__device__ __half2 g_hsh[NMAX * 32];   // (X@W)*dinv[row], fp16, 32 half2 per row
__device__ float  g_agg[NMAX * DD];    // layer-1 output (self+bias, then += messages)

// ---------------------------------------------------------------------------
// CSR build: count -> scan -> fill.  (deg = cnt + 1 gives dinv for free)
__global__ void k_count(const int* __restrict__ dst, int* __restrict__ cnt, int ne) {
    int i = blockIdx.x * blockDim.x + threadIdx.x;
    if (i < ne) atomicAdd(cnt + dst[i], 1);   // no return -> RED
}

__global__ void k_scan1(const int* __restrict__ cnt, int* __restrict__ off,
                        int* __restrict__ bsum, int n) {
    __shared__ int sh[SCAN_B];
    int i = blockIdx.x * SCAN_B + threadIdx.x;
    int v = (i < n) ? cnt[i] : 0;
    sh[threadIdx.x] = v;
    __syncthreads();
#pragma unroll
    for (int d = 1; d < SCAN_B; d <<= 1) {
        int t = (threadIdx.x >= d) ? sh[threadIdx.x - d] : 0;
        __syncthreads();
        sh[threadIdx.x] += t;
        __syncthreads();
    }
    if (i < n) off[i] = sh[threadIdx.x] - v;          // exclusive within block
    if (threadIdx.x == SCAN_B - 1) bsum[blockIdx.x] = sh[SCAN_B - 1];
}

__global__ void k_scan2(int* bsum, int nb) {
    if (blockIdx.x == 0 && threadIdx.x == 0) {
        int run = 0;
        for (int b = 0; b < nb; b++) { int t = bsum[b]; bsum[b] = run; run += t; }
    }
}

// finalize offsets + cursor copy + dinv
__global__ void k_scan3(int* __restrict__ off, const int* __restrict__ bsum,
                        int* __restrict__ cur, const int* __restrict__ cnt,
                        float* __restrict__ dinv, int n) {
    int i = blockIdx.x * blockDim.x + threadIdx.x;
    if (i >= n) return;
    int o = off[i] + bsum[i / SCAN_B];
    off[i] = o;
    cur[i] = o;
    dinv[i] = rsqrtf((float)cnt[i] + 1.0f);
}

__global__ void k_fill(const int* __restrict__ src, const int* __restrict__ dst,
                       int* __restrict__ cur, int* __restrict__ csr, int ne) {
    int i = blockIdx.x * blockDim.x + threadIdx.x;
    if (i < ne) {
        int p = atomicAdd(cur + dst[i], 1);
        csr[p] = src[i];
    }
}

// ---------------------------------------------------------------------------
// Register-tiled GEMM + fused epilogue.
//   h   = f(in) @ W        (f = identity or ReLU)
//   hsh = fp16(h * dinv[row])          -> message features for gather
//   agg = h * dinv^2 + b   (fp32)      -> self-loop + bias (output init)
#define XPAD 68
__global__ __launch_bounds__(256, 2)
void k_gemm_fused(const float* __restrict__ in, const float* __restrict__ W,
                  const float* __restrict__ b, const float* __restrict__ dinv,
                  __half2* __restrict__ hsh, float* __restrict__ agg,
                  int n, int do_relu) {
    extern __shared__ float smem_f[];
    float* Ws = smem_f;                 // 64*64
    float* xs = smem_f + DD * DD;       // 256*XPAD

    int tid = threadIdx.x;
    int cx = tid & 15;
    int ry = tid >> 4;
    int row0 = blockIdx.x * 256;

    for (int i = tid; i < DD * DD; i += 256) Ws[i] = W[i];

    for (int i = tid; i < 256 * 16; i += 256) {
        int r = i >> 4, c4 = i & 15;
        int grow = row0 + r;
        float4 v = make_float4(0.f, 0.f, 0.f, 0.f);
        if (grow < n) v = __ldg(reinterpret_cast<const float4*>(in + (size_t)grow * DD) + c4);
        if (do_relu) {
            v.x = fmaxf(v.x, 0.f); v.y = fmaxf(v.y, 0.f);
            v.z = fmaxf(v.z, 0.f); v.w = fmaxf(v.w, 0.f);
        }
        *reinterpret_cast<float4*>(&xs[r * XPAD + c4 * 4]) = v;
    }
    __syncthreads();

    float4 acc[16];
#pragma unroll
    for (int i = 0; i < 16; i++) acc[i] = make_float4(0.f, 0.f, 0.f, 0.f);

#pragma unroll
    for (int k4 = 0; k4 < 16; k4++) {
        float4 w0 = *reinterpret_cast<const float4*>(&Ws[(k4 * 4 + 0) * DD + cx * 4]);
        float4 w1 = *reinterpret_cast<const float4*>(&Ws[(k4 * 4 + 1) * DD + cx * 4]);
        float4 w2 = *reinterpret_cast<const float4*>(&Ws[(k4 * 4 + 2) * DD + cx * 4]);
        float4 w3 = *reinterpret_cast<const float4*>(&Ws[(k4 * 4 + 3) * DD + cx * 4]);
#pragma unroll
        for (int i = 0; i < 16; i++) {
            float4 xv = *reinterpret_cast<const float4*>(&xs[(ry + 16 * i) * XPAD + k4 * 4]);
            acc[i].x = fmaf(w0.x, xv.x, acc[i].x);
            acc[i].y = fmaf(w0.y, xv.x, acc[i].y);
            acc[i].z = fmaf(w0.z, xv.x, acc[i].z);
            acc[i].w = fmaf(w0.w, xv.x, acc[i].w);
            acc[i].x = fmaf(w1.x, xv.y, acc[i].x);
            acc[i].y = fmaf(w1.y, xv.y, acc[i].y);
            acc[i].z = fmaf(w1.z, xv.y, acc[i].z);
            acc[i].w = fmaf(w1.w, xv.y, acc[i].w);
            acc[i].x = fmaf(w2.x, xv.z, acc[i].x);
            acc[i].y = fmaf(w2.y, xv.z, acc[i].y);
            acc[i].z = fmaf(w2.z, xv.z, acc[i].z);
            acc[i].w = fmaf(w2.w, xv.z, acc[i].w);
            acc[i].x = fmaf(w3.x, xv.w, acc[i].x);
            acc[i].y = fmaf(w3.y, xv.w, acc[i].y);
            acc[i].z = fmaf(w3.z, xv.w, acc[i].z);
            acc[i].w = fmaf(w3.w, xv.w, acc[i].w);
        }
    }

    float4 bv = __ldg(reinterpret_cast<const float4*>(b) + cx);
#pragma unroll
    for (int i = 0; i < 16; i++) {
        int grow = row0 + ry + 16 * i;
        if (grow >= n) continue;
        float di = __ldg(dinv + grow);
        float4 h4 = acc[i];
        float4 hs4 = make_float4(h4.x * di, h4.y * di, h4.z * di, h4.w * di);
        float4 ag4 = make_float4(fmaf(hs4.x, di, bv.x), fmaf(hs4.y, di, bv.y),
                                 fmaf(hs4.z, di, bv.z), fmaf(hs4.w, di, bv.w));
        // fp16 message features (two half2 = one 8B store)
        __half2 p0 = __floats2half2_rn(hs4.x, hs4.y);
        __half2 p1 = __floats2half2_rn(hs4.z, hs4.w);
        uint2 packed;
        packed.x = *reinterpret_cast<unsigned int*>(&p0);
        packed.y = *reinterpret_cast<unsigned int*>(&p1);
        *reinterpret_cast<uint2*>(hsh + (size_t)grow * 32 + cx * 2) = packed;
        *reinterpret_cast<float4*>(agg + (size_t)grow * DD + cx * 4) = ag4;
    }
}

// ---------------------------------------------------------------------------
// Gather-by-destination: one warp per node. lane owns columns [2l, 2l+1].
// out[node] (pre-initialized to self+bias) += sum_e fp16 hsh[src_e] * dinv[node]
__global__ __launch_bounds__(256)
void k_aggregate(const int* __restrict__ csr, const int* __restrict__ off,
                 const int* __restrict__ cnt, const float* __restrict__ dinv,
                 const __half2* __restrict__ hsh, float* __restrict__ out, int n) {
    int node = blockIdx.x * 8 + (threadIdx.x >> 5);
    int lane = threadIdx.x & 31;
    if (node >= n) return;

    int beg = off[node];
    int m = cnt[node];
    float nd = dinv[node];

    float2 acc = *reinterpret_cast<const float2*>(out + (size_t)node * DD + lane * 2);

    int j = 0;
    while (j < m) {
        int rem = m - j;
        int myidx = (lane < rem) ? __ldg(csr + beg + j + lane) : 0;
        int lim = rem < 32 ? rem : 32;
        int t = 0;
        for (; t + 4 <= lim; t += 4) {
            int s0 = __shfl_sync(0xffffffffu, myidx, t + 0);
            int s1 = __shfl_sync(0xffffffffu, myidx, t + 1);
            int s2 = __shfl_sync(0xffffffffu, myidx, t + 2);
            int s3 = __shfl_sync(0xffffffffu, myidx, t + 3);
            __half2 v0 = __ldg(hsh + (size_t)s0 * 32 + lane);
            __half2 v1 = __ldg(hsh + (size_t)s1 * 32 + lane);
            __half2 v2 = __ldg(hsh + (size_t)s2 * 32 + lane);
            __half2 v3 = __ldg(hsh + (size_t)s3 * 32 + lane);
            float2 f0 = __half22float2(v0);
            float2 f1 = __half22float2(v1);
            float2 f2 = __half22float2(v2);
            float2 f3 = __half22float2(v3);
            acc.x = fmaf(f0.x, nd, acc.x); acc.y = fmaf(f0.y, nd, acc.y);
            acc.x = fmaf(f1.x, nd, acc.x); acc.y = fmaf(f1.y, nd, acc.y);
            acc.x = fmaf(f2.x, nd, acc.x); acc.y = fmaf(f2.y, nd, acc.y);
            acc.x = fmaf(f3.x, nd, acc.x); acc.y = fmaf(f3.y, nd, acc.y);
        }
        for (; t < lim; t++) {
            int s = __shfl_sync(0xffffffffu, myidx, t);
            float2 f = __half22float2(__ldg(hsh + (size_t)s * 32 + lane));
            acc.x = fmaf(f.x, nd, acc.x); acc.y = fmaf(f.y, nd, acc.y);
        }
        j += 32;
    }

    *reinterpret_cast<float2*>(out + (size_t)node * DD + lane * 2) = acc;
}

// ---------------------------------------------------------------------------
static void* sym_addr(const void* sym) {
    void* p = nullptr;
    cudaGetSymbolAddress(&p, sym);
    return p;
}

extern "C" void kernel_launch(void* const* d_in, const int* in_sizes, int n_in,
                              void* d_out, int out_size) {
    const float* x  = (const float*)d_in[0];
    const float* W1 = (const float*)d_in[1];
    const float* b1 = (const float*)d_in[2];
    const float* W2 = (const float*)d_in[3];
    const float* b2 = (const float*)d_in[4];
    const int*   e0 = (const int*)d_in[5];   // [2, E]: src row then dst row
    const int*   e1 = (const int*)d_in[6];

    const int N = in_sizes[0] / DD;
    const int E = in_sizes[5] / 2;
    const int NB = (N + SCAN_B - 1) / SCAN_B;

    float*  dinv = (float*)sym_addr(g_dinv);
    int*    cnt  = (int*)sym_addr(g_cnt);
    int*    off  = (int*)sym_addr(g_off);
    int*    cur  = (int*)sym_addr(g_cur);
    int*    bsum = (int*)sym_addr(g_bsum);
    int*    csr  = (int*)sym_addr(g_csr);
    __half2* hsh = (__half2*)sym_addr(g_hsh);
    float*  agg  = (float*)sym_addr(g_agg);
    float*  out  = (float*)d_out;

    const int T = 256;
    int n_grid  = (N + T - 1) / T;
    int e_grid  = (E + T - 1) / T;
    int ag_grid = (N + 7) / 8;
    int gm_grid = (N + 255) / 256;
    size_t gm_smem = (DD * DD + 256 * XPAD) * sizeof(float);

    static int attr_set = 0;
    if (!attr_set) {
        cudaFuncSetAttribute(k_gemm_fused, cudaFuncAttributeMaxDynamicSharedMemorySize,
                             (int)gm_smem);
        attr_set = 1;
    }

    // ---------------- Layer 1 ----------------
    cudaMemsetAsync(cnt, 0, N * sizeof(int));
    k_count<<<e_grid, T>>>(e0 + E, cnt, E);
    k_scan1<<<NB, SCAN_B>>>(cnt, off, bsum, N);
    k_scan2<<<1, 32>>>(bsum, NB);
    k_scan3<<<n_grid, T>>>(off, bsum, cur, cnt, dinv, N);
    k_fill<<<e_grid, T>>>(e0, e0 + E, cur, csr, E);
    k_gemm_fused<<<gm_grid, 256, gm_smem>>>(x, W1, b1, dinv, hsh, agg, N, 0);
    k_aggregate<<<ag_grid, T>>>(csr, off, cnt, dinv, hsh, agg, N);

    // ---------------- Layer 2 ----------------
    cudaMemsetAsync(cnt, 0, N * sizeof(int));
    k_count<<<e_grid, T>>>(e1 + E, cnt, E);
    k_scan1<<<NB, SCAN_B>>>(cnt, off, bsum, N);
    k_scan2<<<1, 32>>>(bsum, NB);
    k_scan3<<<n_grid, T>>>(off, bsum, cur, cnt, dinv, N);
    k_fill<<<e_grid, T>>>(e1, e1 + E, cur, csr, E);
    k_gemm_fused<<<gm_grid, 256, gm_smem>>>(agg, W2, b2, dinv, hsh, out, N, 1);  // ReLU fused
    k_aggregate<<<ag_grid, T>>>(csr, off, cnt, dinv, hsh, out, N);
}